// round 10
// baseline (speedup 1.0000x reference)
#include <cuda_runtime.h>

#define A_ANG 192
#define DDET  576
#define W_IMG 384
#define PADW  672
#define POFF  24

// Scratch (__device__ globals: allocation-free). g_pad is zero-initialized at
// module load; padding slots are never written, so they stay zero across all
// graph replays (out-of-range detector taps contribute exactly 0).
// Valid gather base indices i0 span [-20, 594] (exact bound over pixel disc).
__device__ float2 g_pad[A_ANG * PADW];     // 1.0 MB packed (sino, pred) table
__device__ float  g_img[W_IMG * W_IMG];    // backprojection of raw sino
__device__ float  g_G[625];                // G[d][e] = sum_c w2[c,d]*w1[c,e]
__device__ float  g_B[25];                 // B[d]    = sum_c w2[c,d]*b1[c]
__device__ float  g_W[81];                 // interior 9x9 composite kernel
__device__ float  g_bias[1];               // b2 + sum_d B[d]

// ---------------------------------------------------------------------------
// Kernel 0: build composite-conv tables (1 block, trivial cost)
// ---------------------------------------------------------------------------
__global__ void __launch_bounds__(640) precompute_kernel(
    const float* __restrict__ w1, const float* __restrict__ b1,
    const float* __restrict__ w2, const float* __restrict__ b2)
{
    __shared__ float sG[625];
    const int tid = threadIdx.x;
    if (tid < 625) {
        int d = tid / 25, e = tid % 25;
        float g = 0.0f;
        #pragma unroll
        for (int c = 0; c < 16; c++) g = fmaf(w2[c * 25 + d], w1[c * 25 + e], g);
        sG[tid] = g;
        g_G[tid] = g;
    }
    if (tid < 25) {
        float s = 0.0f;
        #pragma unroll
        for (int c = 0; c < 16; c++) s = fmaf(w2[c * 25 + tid], b1[c], s);
        g_B[tid] = s;
    }
    __syncthreads();
    if (tid < 81) {
        int tty = tid / 9, ttx = tid % 9;
        float w = 0.0f;
        for (int dy = 0; dy < 5; dy++) {
            int ey = tty - dy; if (ey < 0 || ey > 4) continue;
            for (int dx = 0; dx < 5; dx++) {
                int ex = ttx - dx; if (ex < 0 || ex > 4) continue;
                w += sG[(dy * 5 + dx) * 25 + ey * 5 + ex];
            }
        }
        g_W[tid] = w;
    }
    if (tid == 0) {
        float bias = b2[0];
        #pragma unroll
        for (int c = 0; c < 16; c++) {
            float s2 = 0.0f;
            #pragma unroll
            for (int d = 0; d < 25; d++) s2 += w2[c * 25 + d];
            bias = fmaf(s2, b1[c], bias);
        }
        g_bias[0] = bias;
    }
}

// ---------------------------------------------------------------------------
// Kernel 1: composite conv, UNIFORM 9x9 path for every pixel (no divergence).
// Border pixels (within 2 of the image edge) get wrong values here; the
// border_fix_kernel recomputes and overwrites them exactly afterward.
// ---------------------------------------------------------------------------
#define CTX 32
#define CTY 8
__global__ void __launch_bounds__(CTX * CTY) conv12_kernel(
    const float* __restrict__ sino,
    float* __restrict__ sino_pred)
{
    __shared__ float t[CTY + 8][CTX + 8];   // 16 x 40, halo 4, zero-padded
    __shared__ float sW[81];
    __shared__ float sbias;

    const int tid = threadIdx.y * CTX + threadIdx.x;
    if (tid < 81) sW[tid] = g_W[tid];
    if (tid == 81) sbias = g_bias[0];

    const int bx0 = blockIdx.x * CTX, by0 = blockIdx.y * CTY;
    for (int i = tid; i < (CTY + 8) * (CTX + 8); i += CTX * CTY) {
        int ly = i / (CTX + 8), lx = i % (CTX + 8);
        int gy = by0 - 4 + ly, gx = bx0 - 4 + lx;
        float v = 0.0f;
        if ((unsigned)gy < A_ANG && (unsigned)gx < DDET) v = sino[gy * DDET + gx];
        t[ly][lx] = v;
    }
    __syncthreads();

    const int tx = threadIdx.x, ty = threadIdx.y;
    const int gx = bx0 + tx, gy = by0 + ty;
    float acc = sbias;
    #pragma unroll
    for (int a = 0; a < 9; a++)
        #pragma unroll
        for (int b = 0; b < 9; b++)
            acc = fmaf(t[ty + a][tx + b], sW[a * 9 + b], acc);

    sino_pred[gy * DDET + gx] = acc;
    g_pad[gy * PADW + POFF + gx] = make_float2(t[ty + 4][tx + 4], acc);
}

// ---------------------------------------------------------------------------
// Kernel 1b: exact recompute for the 3056 border pixels (within 2 of edge).
// acc = b2 + sum_{d in-bounds}(B[d] + sum_e G[d][e] * sino_zp[...])
// ---------------------------------------------------------------------------
__global__ void __launch_bounds__(256) border_fix_kernel(
    const float* __restrict__ sino,
    const float* __restrict__ b2,
    float* __restrict__ sino_pred)
{
    const int p = blockIdx.x * 256 + threadIdx.x;
    if (p >= A_ANG * DDET) return;
    const int gy = p / DDET, gx = p % DDET;
    const bool interior = (gy >= 2) && (gy <= A_ANG - 3) && (gx >= 2) && (gx <= DDET - 3);
    if (interior) return;

    float acc = b2[0];
    for (int dy = 0; dy < 5; dy++) {
        int hy = gy + dy - 2; if ((unsigned)hy >= A_ANG) continue;
        for (int dx = 0; dx < 5; dx++) {
            int hx = gx + dx - 2; if ((unsigned)hx >= DDET) continue;
            float a2 = g_B[dy * 5 + dx];
            #pragma unroll
            for (int ey = 0; ey < 5; ey++) {
                int sy = hy + ey - 2; if ((unsigned)sy >= A_ANG) continue;
                #pragma unroll
                for (int ex = 0; ex < 5; ex++) {
                    int sx = hx + ex - 2; if ((unsigned)sx >= DDET) continue;
                    a2 = fmaf(__ldg(&sino[sy * DDET + sx]),
                              g_G[(dy * 5 + dx) * 25 + ey * 5 + ex], a2);
                }
            }
            acc += a2;
        }
    }
    sino_pred[p] = acc;
    g_pad[gy * PADW + POFF + gx] = make_float2(__ldg(&sino[p]), acc);
}

// ---------------------------------------------------------------------------
// Kernel 2: dual fan-beam backprojection.
// 32x16 pixel tile per 512-thread block (288 blocks, 2/SM, 32 warps/SM).
// 4-angle unroll = 8 outstanding LDG.64 chains per thread.
// Per-SM L1 working set ~184KB (2 blocks x ~92KB) -> L1-resident.
// ---------------------------------------------------------------------------
__global__ void __launch_bounds__(512) backproj_kernel(
    const float* __restrict__ angles,
    float* __restrict__ img_sino)
{
    __shared__ float2 s_ang[A_ANG];
    const int tid = threadIdx.x;
    if (tid < A_ANG) {
        float sv, cv;
        sincosf(angles[tid], &sv, &cv);
        s_ang[tid] = make_float2(cv, sv);
    }
    __syncthreads();

    // warp footprint 8x4; 16 warps tiled 4 across x, 4 down y -> 32x16 tile
    const int lane = tid & 31, wid = tid >> 5;
    const int lx = lane & 7,  ly = lane >> 3;      // 8 x 4
    const int wx = wid & 3,   wy = wid >> 2;       // 4 x 4
    const int x = blockIdx.x * 32 + wx * 8 + lx;
    const int y = blockIdx.y * 16 + wy * 4 + ly;
    const float X = (float)x - 191.5f;
    const float Y = (float)y - 191.5f;

    float accA = 0.f, accB = 0.f;
    for (int a = 0; a < A_ANG; a += 4) {
        float2 v0[4], v1[4];
        float fr[4];
        #pragma unroll
        for (int j = 0; j < 4; j++) {
            const float2 cs = s_ang[a + j];
            const float px = fmaf(cs.x, X, cs.y * Y);
            const float py = fmaf(-cs.y, X, cs.x * Y);
            const float f  = __fdividef(576.0f, 576.0f + py);
            const float s  = fmaf(px, f, 287.5f);
            const int i0   = __float2int_rd(s);
            fr[j] = s - (float)i0;
            const float2* __restrict__ row = &g_pad[(a + j) * PADW + POFF];
            v0[j] = __ldg(&row[i0]);
            v1[j] = __ldg(&row[i0 + 1]);
        }
        #pragma unroll
        for (int j = 0; j < 4; j++) {
            const float w0 = 1.0f - fr[j];
            accA = fmaf(v0[j].x, w0, accA);
            accA = fmaf(v1[j].x, fr[j], accA);
            accB = fmaf(v0[j].y, w0, accB);
            accB = fmaf(v1[j].y, fr[j], accB);
        }
    }
    const int p = y * W_IMG + x;
    g_img[p]    = accA;
    img_sino[p] = accB;
}

// ---------------------------------------------------------------------------
// Kernel 3: conv3 (2->1, 3x3, pad1), smem-tiled, 32x16 blocks.
// ---------------------------------------------------------------------------
#define DTX 32
#define DTY 16
__global__ void __launch_bounds__(DTX * DTY) conv3_kernel(
    const float* __restrict__ w3, const float* __restrict__ b3,
    const float* __restrict__ img_sino,
    float* __restrict__ img_pred)
{
    __shared__ float sI[DTY + 2][DTX + 2];
    __shared__ float sS[DTY + 2][DTX + 2];
    __shared__ float s_w[18];
    __shared__ float s_b;

    const int tid = threadIdx.y * DTX + threadIdx.x;
    if (tid < 18) s_w[tid] = w3[tid];
    if (tid == 18) s_b = b3[0];

    const int bx0 = blockIdx.x * DTX, by0 = blockIdx.y * DTY;
    for (int i = tid; i < (DTY + 2) * (DTX + 2); i += DTX * DTY) {
        int ly = i / (DTX + 2), lx = i % (DTX + 2);
        int gy = by0 - 1 + ly, gx = bx0 - 1 + lx;
        float vi = 0.0f, vs = 0.0f;
        if ((unsigned)gy < W_IMG && (unsigned)gx < W_IMG) {
            int q = gy * W_IMG + gx;
            vi = g_img[q];
            vs = __ldg(&img_sino[q]);
        }
        sI[ly][lx] = vi;
        sS[ly][lx] = vs;
    }
    __syncthreads();

    const int tx = threadIdx.x, ty = threadIdx.y;
    float acc = s_b;
    #pragma unroll
    for (int ky = 0; ky < 3; ky++)
        #pragma unroll
        for (int kx = 0; kx < 3; kx++) {
            acc = fmaf(sI[ty + ky][tx + kx], s_w[ky * 3 + kx],     acc);
            acc = fmaf(sS[ty + ky][tx + kx], s_w[9 + ky * 3 + kx], acc);
        }
    img_pred[(by0 + ty) * W_IMG + bx0 + tx] = acc;
}

// ---------------------------------------------------------------------------
extern "C" void kernel_launch(void* const* d_in, const int* in_sizes, int n_in,
                              void* d_out, int out_size)
{
    const float* sino   = (const float*)d_in[0];
    const float* angles = (const float*)d_in[1];
    const float* w1     = (const float*)d_in[2];
    const float* b1     = (const float*)d_in[3];
    const float* w2     = (const float*)d_in[4];
    const float* b2     = (const float*)d_in[5];
    const float* w3     = (const float*)d_in[6];
    const float* b3     = (const float*)d_in[7];

    float* out       = (float*)d_out;
    float* sino_pred = out;                               // 192*576 = 110592
    float* img_sino  = out + A_ANG * DDET;                // 384*384 = 147456
    float* img_pred  = out + A_ANG * DDET + W_IMG * W_IMG;

    precompute_kernel<<<1, 640>>>(w1, b1, w2, b2);

    dim3 grid1(DDET / CTX, A_ANG / CTY);
    dim3 block1(CTX, CTY);
    conv12_kernel<<<grid1, block1>>>(sino, sino_pred);

    border_fix_kernel<<<(A_ANG * DDET + 255) / 256, 256>>>(sino, b2, sino_pred);

    dim3 grid2(W_IMG / 32, W_IMG / 16);
    backproj_kernel<<<grid2, 512>>>(angles, img_sino);

    dim3 grid3(W_IMG / DTX, W_IMG / DTY);
    dim3 block3(DTX, DTY);
    conv3_kernel<<<grid3, block3>>>(w3, b3, img_sino, img_pred);
}